// round 3
// baseline (speedup 1.0000x reference)
#include <cuda_runtime.h>
#include <cstdint>

#define NN 100000
#define NE 1600000
#define DF 64

// Scratch (allocation-free rule: __device__ globals)
__device__ int g_cnt[NN];        // degree counts, then bucket cursors
__device__ int g_off[NN + 1];    // CSR offsets
__device__ int g_eidx[NE];       // CSR: src index per slot, grouped by dst

// ---------------------------------------------------------------------------
// K0: zero the degree counters (graph replays require re-zeroing)
// ---------------------------------------------------------------------------
__global__ void zero_kernel() {
    int tid = blockIdx.x * blockDim.x + threadIdx.x;
    if (tid < NN) g_cnt[tid] = 0;
}

// ---------------------------------------------------------------------------
// K1: count in-degree per dst (int RED, cheap)
// ---------------------------------------------------------------------------
__global__ void count_kernel(const int* __restrict__ dst, int E) {
    int e = blockIdx.x * blockDim.x + threadIdx.x;
    if (e < E) atomicAdd(&g_cnt[dst[e]], 1);
}

// ---------------------------------------------------------------------------
// K2: single-block exclusive scan over g_cnt -> g_off (and reset g_cnt to the
// cursor start). 1024 threads x 4 elems/iter, serial carry across chunks.
// ---------------------------------------------------------------------------
__global__ void __launch_bounds__(1024, 1)
scan_kernel() {
    __shared__ int sh[1024];
    __shared__ int s_carry;
    const int tid = threadIdx.x;
    if (tid == 0) s_carry = 0;
    __syncthreads();

    for (int base = 0; base < NN; base += 4096) {
        int idx0 = base + tid * 4;
        int v[4];
        int sum = 0;
#pragma unroll
        for (int u = 0; u < 4; u++) {
            int i = idx0 + u;
            v[u] = (i < NN) ? g_cnt[i] : 0;
            sum += v[u];
        }
        sh[tid] = sum;
        __syncthreads();
        // Hillis-Steele inclusive scan on thread sums
        for (int ofs = 1; ofs < 1024; ofs <<= 1) {
            int t = (tid >= ofs) ? sh[tid - ofs] : 0;
            __syncthreads();
            sh[tid] += t;
            __syncthreads();
        }
        int excl = sh[tid] - sum + s_carry;
        int total = sh[1023];
#pragma unroll
        for (int u = 0; u < 4; u++) {
            int i = idx0 + u;
            if (i < NN) {
                g_off[i] = excl;
                g_cnt[i] = excl;   // becomes the bucket cursor
                excl += v[u];
            }
        }
        __syncthreads();
        if (tid == 0) s_carry += total;
        __syncthreads();
    }
    if (tid == 0) g_off[NN] = s_carry;
}

// ---------------------------------------------------------------------------
// K3: bucket edges into CSR slots (int ATOM cursor alloc; order irrelevant)
// ---------------------------------------------------------------------------
__global__ void bucket_kernel(const int* __restrict__ src,
                              const int* __restrict__ dst, int E) {
    int e = blockIdx.x * blockDim.x + threadIdx.x;
    if (e < E) {
        int pos = atomicAdd(&g_cnt[dst[e]], 1);
        g_eidx[pos] = src[e];
    }
}

// ---------------------------------------------------------------------------
// K4: fused gather-mean + GEMM + ReLU. One warp per node.
// Lane l accumulates feature cols {2l, 2l+1} over the node's edge list
// (coalesced 256B float2 gathers, L2-resident). Then out[j] for j = lane and
// lane+32 via smem-transposed W (conflict-free LDS) and shfl-broadcast x.
// ---------------------------------------------------------------------------
__global__ void __launch_bounds__(256, 4)
fused_kernel(const float* __restrict__ h,
             const float* __restrict__ W, const float* __restrict__ b,
             float* __restrict__ out, int N) {
    __shared__ float Wt[DF * DF];   // Wt[k*64 + j] = W[j*64 + k]
    __shared__ float bs[DF];

    const int tid = threadIdx.x;
    // Load + transpose W into smem (once per block)
    for (int idx = tid; idx < DF * DF; idx += 256) {
        int j = idx >> 6, k = idx & 63;
        Wt[k * DF + j] = W[idx];
    }
    if (tid < DF) bs[tid] = b[tid];
    __syncthreads();

    const int lane = tid & 31;
    const int warp = tid >> 5;
    const int node = blockIdx.x * 8 + warp;
    if (node >= N) return;

    const int beg = g_off[node];
    const int end = g_off[node + 1];
    const int deg = end - beg;

    float s0 = 0.f, s1 = 0.f;
    int i = beg;
    for (; i + 1 < end; i += 2) {            // 2-way unroll for MLP
        int sA = g_eidx[i];
        int sB = g_eidx[i + 1];
        float2 va = *reinterpret_cast<const float2*>(h + (size_t)sA * DF + lane * 2);
        float2 vb = *reinterpret_cast<const float2*>(h + (size_t)sB * DF + lane * 2);
        s0 += va.x + vb.x;
        s1 += va.y + vb.y;
    }
    if (i < end) {
        int sA = g_eidx[i];
        float2 va = *reinterpret_cast<const float2*>(h + (size_t)sA * DF + lane * 2);
        s0 += va.x;
        s1 += va.y;
    }

    const float inv = (deg > 0) ? (1.0f / (float)deg) : 0.0f;
    const float x0 = s0 * inv;   // x[2*lane]
    const float x1 = s1 * inv;   // x[2*lane+1]

    float a0 = bs[lane];
    float a1 = bs[lane + 32];
#pragma unroll
    for (int k = 0; k < 32; k++) {
        float xa = __shfl_sync(0xffffffffu, x0, k);   // x[2k]
        float xb = __shfl_sync(0xffffffffu, x1, k);   // x[2k+1]
        a0 = fmaf(Wt[(2 * k) * DF + lane],      xa, a0);
        a0 = fmaf(Wt[(2 * k + 1) * DF + lane],  xb, a0);
        a1 = fmaf(Wt[(2 * k) * DF + lane + 32], xa, a1);
        a1 = fmaf(Wt[(2 * k + 1) * DF + lane + 32], xb, a1);
    }

    float* o = out + (size_t)node * DF;
    o[lane]      = (deg > 0) ? fmaxf(a0, 0.0f) : 0.0f;
    o[lane + 32] = (deg > 0) ? fmaxf(a1, 0.0f) : 0.0f;
}

// ---------------------------------------------------------------------------
extern "C" void kernel_launch(void* const* d_in, const int* in_sizes, int n_in,
                              void* d_out, int out_size) {
    const float* h   = (const float*)d_in[0];
    const int*   src = (const int*)d_in[1];
    const int*   dst = (const int*)d_in[2];
    const float* W   = (const float*)d_in[3];
    const float* b   = (const float*)d_in[4];
    float* out = (float*)d_out;

    const int N = in_sizes[0] / DF;   // 100000
    int E = in_sizes[1];              // 1600000
    if (E > NE) E = NE;

    zero_kernel<<<(NN + 255) / 256, 256>>>();
    count_kernel<<<(E + 255) / 256, 256>>>(dst, E);
    scan_kernel<<<1, 1024>>>();
    bucket_kernel<<<(E + 255) / 256, 256>>>(src, dst, E);
    fused_kernel<<<(N + 7) / 8, 256>>>(h, W, b, out, N);
}

// round 4
// speedup vs baseline: 2.7276x; 2.7276x over previous
#include <cuda_runtime.h>
#include <cstdint>

#define NN 100000
#define NE 1600000
#define DF 64
#define NB 98   // ceil(NN / 1024)

// Scratch (allocation-free rule: __device__ globals)
__device__ int g_cnt[NN];        // degree counts, then bucket cursors
__device__ int g_off[NN + 1];    // CSR offsets
__device__ int g_bsum[128];      // per-block sums for the scan
__device__ int g_eidx[NE];       // CSR: src index per slot, grouped by dst

// ---------------------------------------------------------------------------
// K0: zero degree counters (graph replays require re-zeroing)
// ---------------------------------------------------------------------------
__global__ void zero_kernel() {
    int tid = blockIdx.x * blockDim.x + threadIdx.x;
    if (tid < NN) g_cnt[tid] = 0;
}

// ---------------------------------------------------------------------------
// K1: count in-degree per dst. 4 edges/thread (int4 load) for MLP.
// ---------------------------------------------------------------------------
__global__ void count_kernel(const int* __restrict__ dst, int E) {
    int i = (blockIdx.x * blockDim.x + threadIdx.x) * 4;
    if (i + 3 < E) {
        int4 d = *reinterpret_cast<const int4*>(dst + i);
        atomicAdd(&g_cnt[d.x], 1);
        atomicAdd(&g_cnt[d.y], 1);
        atomicAdd(&g_cnt[d.z], 1);
        atomicAdd(&g_cnt[d.w], 1);
    } else {
        for (int u = 0; u < 4 && i + u < E; u++)
            atomicAdd(&g_cnt[dst[i + u]], 1);
    }
}

// ---------------------------------------------------------------------------
// K2a: per-block (1024 elems) local exclusive scan of g_cnt -> g_off,
//      block totals -> g_bsum.
// ---------------------------------------------------------------------------
__global__ void __launch_bounds__(1024)
scanA_kernel() {
    __shared__ int wsum[32];
    const int tid = threadIdx.x;
    const int lane = tid & 31;
    const int wid = tid >> 5;
    int gid = blockIdx.x * 1024 + tid;

    int v = (gid < NN) ? g_cnt[gid] : 0;
    int x = v;
#pragma unroll
    for (int o = 1; o < 32; o <<= 1) {
        int t = __shfl_up_sync(0xffffffffu, x, o);
        if (lane >= o) x += t;
    }
    if (lane == 31) wsum[wid] = x;
    __syncthreads();
    if (tid < 32) {
        int y = wsum[tid];
#pragma unroll
        for (int o = 1; o < 32; o <<= 1) {
            int t = __shfl_up_sync(0xffffffffu, y, o);
            if (tid >= o) y += t;
        }
        wsum[tid] = y;
    }
    __syncthreads();
    int base = (wid > 0) ? wsum[wid - 1] : 0;
    int incl = x + base;
    if (gid < NN) g_off[gid] = incl - v;           // local exclusive
    if (tid == 1023) g_bsum[blockIdx.x] = incl;    // block total
}

// ---------------------------------------------------------------------------
// K2b: one warp scans the NB block sums (exclusive), writes total to g_off[NN]
// ---------------------------------------------------------------------------
__global__ void scanB_kernel() {
    int lane = threadIdx.x;   // 32 threads
    int v[4];
    int s = 0;
#pragma unroll
    for (int u = 0; u < 4; u++) {
        int i = lane * 4 + u;
        v[u] = (i < NB) ? g_bsum[i] : 0;
        s += v[u];
    }
    int x = s;
#pragma unroll
    for (int o = 1; o < 32; o <<= 1) {
        int t = __shfl_up_sync(0xffffffffu, x, o);
        if (lane >= o) x += t;
    }
    int excl = x - s;
#pragma unroll
    for (int u = 0; u < 4; u++) {
        int i = lane * 4 + u;
        if (i < NB) { g_bsum[i] = excl; excl += v[u]; }
    }
    if (lane == 31) g_off[NN] = x;   // grand total (== E)
}

// ---------------------------------------------------------------------------
// K2c: add block base to local scans; init bucket cursors
// ---------------------------------------------------------------------------
__global__ void __launch_bounds__(1024)
scanC_kernel() {
    int gid = blockIdx.x * 1024 + threadIdx.x;
    if (gid < NN) {
        int o = g_off[gid] + g_bsum[blockIdx.x];
        g_off[gid] = o;
        g_cnt[gid] = o;
    }
}

// ---------------------------------------------------------------------------
// K3: bucket edges into CSR slots. 4 edges/thread (int4 loads) for MLP.
// ---------------------------------------------------------------------------
__global__ void bucket_kernel(const int* __restrict__ src,
                              const int* __restrict__ dst, int E) {
    int i = (blockIdx.x * blockDim.x + threadIdx.x) * 4;
    if (i + 3 < E) {
        int4 s = *reinterpret_cast<const int4*>(src + i);
        int4 d = *reinterpret_cast<const int4*>(dst + i);
        int p0 = atomicAdd(&g_cnt[d.x], 1);
        int p1 = atomicAdd(&g_cnt[d.y], 1);
        int p2 = atomicAdd(&g_cnt[d.z], 1);
        int p3 = atomicAdd(&g_cnt[d.w], 1);
        g_eidx[p0] = s.x;
        g_eidx[p1] = s.y;
        g_eidx[p2] = s.z;
        g_eidx[p3] = s.w;
    } else {
        for (int u = 0; u < 4 && i + u < E; u++) {
            int pos = atomicAdd(&g_cnt[dst[i + u]], 1);
            g_eidx[pos] = src[i + u];
        }
    }
}

// ---------------------------------------------------------------------------
// K4: fused gather-mean + GEMM + ReLU. Persistent blocks; one warp per node.
// Warp loads 32 edge indices in ONE coalesced LDG (lane-parallel), then
// shfl-broadcasts them; h-row gathers for different edges are independent
// (MLP=4 via unroll). Then out = relu(W @ mean + b) via padded smem-transposed
// W (conflict-free) and shfl-broadcast x.
// ---------------------------------------------------------------------------
__global__ void __launch_bounds__(256)
fused_kernel(const float* __restrict__ h,
             const float* __restrict__ W, const float* __restrict__ b,
             float* __restrict__ out, int N) {
    __shared__ float Wt[DF * 65];   // Wt[k*65 + j] = W[j*64 + k] (padded)
    __shared__ float bs[DF];

    const int tid = threadIdx.x;
    for (int idx = tid; idx < DF * DF; idx += 256) {
        int j = idx >> 6, k = idx & 63;
        Wt[k * 65 + j] = W[idx];    // coalesced read, conflict-free write
    }
    if (tid < DF) bs[tid] = b[tid];
    __syncthreads();

    const int lane = tid & 31;
    const int warp = tid >> 5;
    const unsigned FULL = 0xffffffffu;

    for (int node = blockIdx.x * 8 + warp; node < N; node += gridDim.x * 8) {
        const int beg = g_off[node];
        const int end = g_off[node + 1];
        const int deg = end - beg;

        float s0 = 0.f, s1 = 0.f;
        for (int base = beg; base < end; base += 32) {
            int idx = base + lane;
            int si = (idx < end) ? g_eidx[idx] : 0;   // one coalesced load / 32 edges
            int n = min(32, end - base);
            int t = 0;
            for (; t + 3 < n; t += 4) {               // MLP = 4 independent gathers
                int ia = __shfl_sync(FULL, si, t);
                int ib = __shfl_sync(FULL, si, t + 1);
                int ic = __shfl_sync(FULL, si, t + 2);
                int id = __shfl_sync(FULL, si, t + 3);
                float2 va = *reinterpret_cast<const float2*>(h + (size_t)ia * DF + lane * 2);
                float2 vb = *reinterpret_cast<const float2*>(h + (size_t)ib * DF + lane * 2);
                float2 vc = *reinterpret_cast<const float2*>(h + (size_t)ic * DF + lane * 2);
                float2 vd = *reinterpret_cast<const float2*>(h + (size_t)id * DF + lane * 2);
                s0 += (va.x + vb.x) + (vc.x + vd.x);
                s1 += (va.y + vb.y) + (vc.y + vd.y);
            }
            for (; t < n; t++) {
                int ia = __shfl_sync(FULL, si, t);
                float2 va = *reinterpret_cast<const float2*>(h + (size_t)ia * DF + lane * 2);
                s0 += va.x;
                s1 += va.y;
            }
        }

        const float inv = (deg > 0) ? (1.0f / (float)deg) : 0.0f;
        const float x0 = s0 * inv;   // x[2*lane]
        const float x1 = s1 * inv;   // x[2*lane+1]

        float a0 = bs[lane];
        float a1 = bs[lane + 32];
#pragma unroll
        for (int k = 0; k < 32; k++) {
            float xa = __shfl_sync(FULL, x0, k);     // x[2k]
            float xb = __shfl_sync(FULL, x1, k);     // x[2k+1]
            a0 = fmaf(Wt[(2 * k) * 65 + lane],          xa, a0);
            a0 = fmaf(Wt[(2 * k + 1) * 65 + lane],      xb, a0);
            a1 = fmaf(Wt[(2 * k) * 65 + lane + 32],     xa, a1);
            a1 = fmaf(Wt[(2 * k + 1) * 65 + lane + 32], xb, a1);
        }

        float* o = out + (size_t)node * DF;
        o[lane]      = (deg > 0) ? fmaxf(a0, 0.0f) : 0.0f;
        o[lane + 32] = (deg > 0) ? fmaxf(a1, 0.0f) : 0.0f;
    }
}

// ---------------------------------------------------------------------------
extern "C" void kernel_launch(void* const* d_in, const int* in_sizes, int n_in,
                              void* d_out, int out_size) {
    const float* h   = (const float*)d_in[0];
    const int*   src = (const int*)d_in[1];
    const int*   dst = (const int*)d_in[2];
    const float* W   = (const float*)d_in[3];
    const float* b   = (const float*)d_in[4];
    float* out = (float*)d_out;

    const int N = in_sizes[0] / DF;   // 100000
    int E = in_sizes[1];              // 1600000
    if (E > NE) E = NE;

    zero_kernel<<<(NN + 255) / 256, 256>>>();
    count_kernel<<<(E / 4 + 255) / 256, 256>>>(dst, E);
    scanA_kernel<<<NB, 1024>>>();
    scanB_kernel<<<1, 32>>>();
    scanC_kernel<<<NB, 1024>>>();
    bucket_kernel<<<(E / 4 + 255) / 256, 256>>>(src, dst, E);
    fused_kernel<<<1184, 256>>>(h, W, b, out, N);
}